// round 13
// baseline (speedup 1.0000x reference)
#include <cuda_runtime.h>
#include <cuda_bf16.h>
#include <cstdint>
#include <cstddef>

#define NN   200000
#define EE   800000
#define FIN  128
#define GG   8000
#define SCAN_B 512

// ---------------- device scratch ----------------
__device__ float g_bufA[(size_t)NN * 128];
__device__ float g_bufB[(size_t)NN * 128];
__device__ float g_bufC[(size_t)NN * 128];
__device__ float g_dis[NN];
__device__ int   g_cnt[NN];
__device__ int   g_rowptr[NN + 1];
__device__ int   g_fill[NN];
__device__ float2 g_csr2[EE];          // packed {src_bits, dis[src]}
__device__ int   g_bsum[SCAN_B];
__device__ int   g_boff[SCAN_B];
__device__ int   g_gptr[GG + 1];
__device__ int   g_nodeg[NN];
__device__ float g_na[GG * 128];
__device__ float g_nb[GG * 128];
__device__ int   g_pool[GG * 128];     // float bits; post-relu >= 0 so int max == float max
__device__ int   g_ei64;
__device__ int   g_b64;

__device__ __forceinline__ long long ld_idx(const void* p, long long i, int is64) {
    if (is64) return ((const long long*)p)[i];
    return (long long)((const int*)p)[i];
}

// ---------------- init (cnt + pool) + dtype detection (block 0) ----------
__global__ void init_kernel(const void* ei, const void* batch) {
    int i = blockIdx.x * blockDim.x + threadIdx.x;
    if (i < NN) g_cnt[i] = 0;
    if (i < GG * 128) g_pool[i] = 0;
    if (blockIdx.x == 0 && threadIdx.x < 32) {
        int lane = threadIdx.x;
        long long v = ((const long long*)ei)[lane];
        unsigned bad1 = __ballot_sync(0xffffffffu, v < 0 || v >= NN);
        long long q = ((const long long*)batch)[lane];
        unsigned bad2 = __ballot_sync(0xffffffffu, q < 0 || q >= GG);
        if (lane == 0) {
            g_ei64 = (bad1 == 0u);
            g_b64  = (bad2 == 0u);
        }
    }
}

// ---------------- batchinfo (nodeg + gptr) + degree count, merged --------
__global__ void graph_kernel(const void* __restrict__ batch,
                             const void* __restrict__ ei) {
    int i = blockIdx.x * blockDim.x + threadIdx.x;
    if (i < NN) {
        int is64 = g_b64;
        int bi = (int)ld_idx(batch, i, is64);
        g_nodeg[i] = bi;
        if (i == 0) {
            for (int g = 0; g <= bi; g++) g_gptr[g] = 0;
        } else {
            int bp = (int)ld_idx(batch, i - 1, is64);
            for (int g = bp + 1; g <= bi; g++) g_gptr[g] = i;
        }
        if (i == NN - 1) {
            for (int g = bi + 1; g <= GG; g++) g_gptr[g] = NN;
        }
    }
    if (i < EE) {
        int dst = (int)ld_idx(ei, (long long)EE + i, g_ei64);
        atomicAdd(&g_cnt[dst], 1);
    }
}

// ---------------- exclusive scan of g_cnt -> g_rowptr (+ dis fused) ------
__global__ void scan1_kernel() {
    __shared__ int s[SCAN_B];
    int tid = threadIdx.x;
    int i = blockIdx.x * SCAN_B + tid;
    int v = (i < NN) ? g_cnt[i] : 0;
    if (i < NN) g_dis[i] = rsqrtf(1.0f + (float)v);
    s[tid] = v;
    __syncthreads();
    for (int off = 1; off < SCAN_B; off <<= 1) {
        int t = (tid >= off) ? s[tid - off] : 0;
        __syncthreads();
        s[tid] += t;
        __syncthreads();
    }
    if (i < NN) g_rowptr[i] = s[tid] - v;
    if (tid == SCAN_B - 1) g_bsum[blockIdx.x] = s[tid];
}
__global__ void scan2_kernel(int nb) {
    __shared__ int s[SCAN_B];
    int tid = threadIdx.x;
    int v = (tid < nb) ? g_bsum[tid] : 0;
    s[tid] = v;
    __syncthreads();
    for (int off = 1; off < SCAN_B; off <<= 1) {
        int t = (tid >= off) ? s[tid - off] : 0;
        __syncthreads();
        s[tid] += t;
        __syncthreads();
    }
    g_boff[tid] = s[tid] - v;
}
__global__ void scan3_kernel() {
    int i = blockIdx.x * blockDim.x + threadIdx.x;
    if (i < NN) {
        int v = g_rowptr[i] + g_boff[i / SCAN_B];
        g_rowptr[i] = v;
        g_fill[i] = v;
    }
    if (i == 0) g_rowptr[NN] = EE;
}

// ---------------- CSR fill (packed) ----------------
__global__ void fill_kernel(const void* __restrict__ ei) {
    int i = blockIdx.x * blockDim.x + threadIdx.x;
    if (i >= EE) return;
    int is64 = g_ei64;
    int src = (int)ld_idx(ei, i, is64);
    int dst = (int)ld_idx(ei, (long long)EE + i, is64);
    int pos = atomicAdd(&g_fill[dst], 1);
    g_csr2[pos] = make_float2(__int_as_float(src), g_dis[src]);
}

// ---------------- instance norm stats -> affine (v*na + nb) --------------
__global__ void stats_kernel(const float* __restrict__ x,
                             const float* __restrict__ wp,
                             const float* __restrict__ bp) {
    int g = blockIdx.x;
    int c = threadIdx.x;   // 128
    int s = g_gptr[g], e = g_gptr[g + 1];
    if (s >= e) { g_na[g * 128 + c] = 0.f; g_nb[g * 128 + c] = 0.f; return; }
    float w = wp[0], b = bp[0];
    float sum = 0.f, sq = 0.f;
    for (int i = s; i < e; i++) {
        float v = x[(size_t)i * FIN + c];
        sum += v; sq += v * v;
    }
    float cnt  = (float)(e - s);
    float mean = sum / cnt;
    float var  = sq / cnt - mean * mean;
    float inv  = rsqrtf(var + 1e-5f);
    float na = inv * w;
    g_na[g * 128 + c] = na;
    g_nb[g * 128 + c] = b - mean * na;
}

// ---------------- bf16x3 split tensor-core GEMM (pipelined X stage) ------
// Y[r, col0+c] = sum_k X[r,k] * W[k, col0+c]   (only lo*lo dropped)
// 256 threads / 8 warps, 128 rows per block; warp w -> rows [w*16, w*16+16).
// X chunk k+1 is prefetched into registers during chunk k's mma phase.
// EPI: 0 plain, 1 bias+relu, 2 bias+relu + fused per-graph max-pool (NO Y),
//      3 bias only.  NORM: fuse instnorm affine (CIN must be 128).
template<int CIN, int COUT, bool NORM, int EPI>
__global__ __launch_bounds__(256, 2)
void mma_gemm(const float* __restrict__ X, const float* __restrict__ W,
              int ldw, const float* __restrict__ bias,
              float* __restrict__ Y, int ldy, int nrows) {
    constexpr int KCH = 32;
    constexpr int ST  = 40;              // padded stride (bf16), 80B rows
    constexpr int NT  = COUT / 8;        // n-tiles (even)
    constexpr int PSLOT = (EPI == 2) ? 32 : 1;
    constexpr int KQ  = KCH / 4;         // 8 float4 per row
    constexpr int XJ  = 128 * KQ / 256;  // 4 float4 per thread per chunk

    __shared__ __align__(16) __nv_bfloat16 sXhi[128 * ST];
    __shared__ __align__(16) __nv_bfloat16 sXlo[128 * ST];
    __shared__ __align__(16) __nv_bfloat16 sWhi[COUT * ST];
    __shared__ __align__(16) __nv_bfloat16 sWlo[COUT * ST];
    __shared__ int sPool[PSLOT * 128];

    int tid = threadIdx.x;
    int wid = tid >> 5;
    int lane = tid & 31;
    int r0 = blockIdx.x * 128;
    int col0 = blockIdx.y * COUT;

    if (EPI == 2) {
        for (int i = tid; i < PSLOT * 128; i += 256) sPool[i] = 0;
    }

    float acc[NT][4];
#pragma unroll
    for (int n = 0; n < NT; n++)
#pragma unroll
        for (int j = 0; j < 4; j++) acc[n][j] = 0.f;

    // ldmatrix base addresses
    int arow = lane & 15;
    int akoff = (lane >> 4) * 8;
    unsigned aAhi = (unsigned)__cvta_generic_to_shared(
        &sXhi[(wid * 16 + arow) * ST + akoff]);
    unsigned aAlo = (unsigned)__cvta_generic_to_shared(
        &sXlo[(wid * 16 + arow) * ST + akoff]);
    // B paired x4: tiles n, n+1 in one ldmatrix
    int brow = (lane & 7) + (lane >> 4) * 8;
    int bkoff = ((lane >> 3) & 1) * 8;
    unsigned aBhi = (unsigned)__cvta_generic_to_shared(&sWhi[brow * ST + bkoff]);
    unsigned aBlo = (unsigned)__cvta_generic_to_shared(&sWlo[brow * ST + bkoff]);

    // X prefetch registers (chunk-invariant per-thread tile coords)
    float4 xp[XJ];
    int xr_rl[XJ], xr_kq[XJ];
#pragma unroll
    for (int j = 0; j < XJ; j++) {
        int i = tid + j * 256;
        xr_rl[j] = i / KQ;
        xr_kq[j] = i % KQ;
    }

    // prefetch chunk 0
#pragma unroll
    for (int j = 0; j < XJ; j++) {
        int row = r0 + xr_rl[j];
        xp[j] = (row < nrows)
            ? *(const float4*)&X[(size_t)row * CIN + xr_kq[j] * 4]
            : make_float4(0.f, 0.f, 0.f, 0.f);
    }

    for (int k0 = 0; k0 < CIN; k0 += KCH) {
        // ---- store prefetched X chunk: norm + split -> smem ----
#pragma unroll
        for (int j = 0; j < XJ; j++) {
            float4 v = xp[j];
            if (NORM) {
                int row = r0 + xr_rl[j];
                if (row < nrows) {
                    int g = g_nodeg[row];
                    const float4 na = *(const float4*)&g_na[g * 128 + k0 + xr_kq[j] * 4];
                    const float4 nb = *(const float4*)&g_nb[g * 128 + k0 + xr_kq[j] * 4];
                    v.x = v.x * na.x + nb.x; v.y = v.y * na.y + nb.y;
                    v.z = v.z * na.z + nb.z; v.w = v.w * na.w + nb.w;
                }
            }
            __nv_bfloat162 h01 = __floats2bfloat162_rn(v.x, v.y);
            __nv_bfloat162 h23 = __floats2bfloat162_rn(v.z, v.w);
            __nv_bfloat162 l01 = __floats2bfloat162_rn(
                v.x - __bfloat162float(h01.x), v.y - __bfloat162float(h01.y));
            __nv_bfloat162 l23 = __floats2bfloat162_rn(
                v.z - __bfloat162float(h23.x), v.w - __bfloat162float(h23.y));
            int base = xr_rl[j] * ST + xr_kq[j] * 4;
            uint2 hu, lu;
            hu.x = *(unsigned*)&h01; hu.y = *(unsigned*)&h23;
            lu.x = *(unsigned*)&l01; lu.y = *(unsigned*)&l23;
            *(uint2*)&sXhi[base] = hu;
            *(uint2*)&sXlo[base] = lu;
        }
        // ---- W chunk: [k][c] -> Wt [c][k], coalesced loads, bf162 stores ----
        for (int i = tid; i < COUT * (KCH / 2); i += 256) {
            int c  = i % COUT;
            int kp = i / COUT;
            int k  = kp * 2;
            float w0 = W[(size_t)(k0 + k)     * ldw + col0 + c];
            float w1 = W[(size_t)(k0 + k + 1) * ldw + col0 + c];
            __nv_bfloat162 h = __floats2bfloat162_rn(w0, w1);
            __nv_bfloat162 l = __floats2bfloat162_rn(
                w0 - __bfloat162float(h.x), w1 - __bfloat162float(h.y));
            *(__nv_bfloat162*)&sWhi[c * ST + k] = h;
            *(__nv_bfloat162*)&sWlo[c * ST + k] = l;
        }
        __syncthreads();

        // ---- prefetch next X chunk (overlaps with mma phase) ----
        if (k0 + KCH < CIN) {
#pragma unroll
            for (int j = 0; j < XJ; j++) {
                int row = r0 + xr_rl[j];
                xp[j] = (row < nrows)
                    ? *(const float4*)&X[(size_t)row * CIN + k0 + KCH + xr_kq[j] * 4]
                    : make_float4(0.f, 0.f, 0.f, 0.f);
            }
        }

#pragma unroll
        for (int ks = 0; ks < KCH / 16; ks++) {
            unsigned ah0, ah1, ah2, ah3, al0, al1, al2, al3;
            asm volatile("ldmatrix.sync.aligned.m8n8.x4.shared.b16 {%0,%1,%2,%3}, [%4];"
                         : "=r"(ah0), "=r"(ah1), "=r"(ah2), "=r"(ah3)
                         : "r"(aAhi + ks * 32u));
            asm volatile("ldmatrix.sync.aligned.m8n8.x4.shared.b16 {%0,%1,%2,%3}, [%4];"
                         : "=r"(al0), "=r"(al1), "=r"(al2), "=r"(al3)
                         : "r"(aAlo + ks * 32u));
#pragma unroll
            for (int np = 0; np < NT / 2; np++) {
                unsigned bh0, bh1, bh2, bh3, bl0, bl1, bl2, bl3;
                unsigned boff = (unsigned)(np * 16 * ST * 2) + ks * 32u;
                asm volatile("ldmatrix.sync.aligned.m8n8.x4.shared.b16 {%0,%1,%2,%3}, [%4];"
                             : "=r"(bh0), "=r"(bh1), "=r"(bh2), "=r"(bh3)
                             : "r"(aBhi + boff));
                asm volatile("ldmatrix.sync.aligned.m8n8.x4.shared.b16 {%0,%1,%2,%3}, [%4];"
                             : "=r"(bl0), "=r"(bl1), "=r"(bl2), "=r"(bl3)
                             : "r"(aBlo + boff));
                int n0 = np * 2, n1 = np * 2 + 1;
                asm volatile("mma.sync.aligned.m16n8k16.row.col.f32.bf16.bf16.f32 "
                             "{%0,%1,%2,%3},{%4,%5,%6,%7},{%8,%9},{%0,%1,%2,%3};"
                             : "+f"(acc[n0][0]), "+f"(acc[n0][1]), "+f"(acc[n0][2]), "+f"(acc[n0][3])
                             : "r"(ah0), "r"(ah1), "r"(ah2), "r"(ah3), "r"(bh0), "r"(bh1));
                asm volatile("mma.sync.aligned.m16n8k16.row.col.f32.bf16.bf16.f32 "
                             "{%0,%1,%2,%3},{%4,%5,%6,%7},{%8,%9},{%0,%1,%2,%3};"
                             : "+f"(acc[n0][0]), "+f"(acc[n0][1]), "+f"(acc[n0][2]), "+f"(acc[n0][3])
                             : "r"(al0), "r"(al1), "r"(al2), "r"(al3), "r"(bh0), "r"(bh1));
                asm volatile("mma.sync.aligned.m16n8k16.row.col.f32.bf16.bf16.f32 "
                             "{%0,%1,%2,%3},{%4,%5,%6,%7},{%8,%9},{%0,%1,%2,%3};"
                             : "+f"(acc[n0][0]), "+f"(acc[n0][1]), "+f"(acc[n0][2]), "+f"(acc[n0][3])
                             : "r"(ah0), "r"(ah1), "r"(ah2), "r"(ah3), "r"(bl0), "r"(bl1));
                asm volatile("mma.sync.aligned.m16n8k16.row.col.f32.bf16.bf16.f32 "
                             "{%0,%1,%2,%3},{%4,%5,%6,%7},{%8,%9},{%0,%1,%2,%3};"
                             : "+f"(acc[n1][0]), "+f"(acc[n1][1]), "+f"(acc[n1][2]), "+f"(acc[n1][3])
                             : "r"(ah0), "r"(ah1), "r"(ah2), "r"(ah3), "r"(bh2), "r"(bh3));
                asm volatile("mma.sync.aligned.m16n8k16.row.col.f32.bf16.bf16.f32 "
                             "{%0,%1,%2,%3},{%4,%5,%6,%7},{%8,%9},{%0,%1,%2,%3};"
                             : "+f"(acc[n1][0]), "+f"(acc[n1][1]), "+f"(acc[n1][2]), "+f"(acc[n1][3])
                             : "r"(al0), "r"(al1), "r"(al2), "r"(al3), "r"(bh2), "r"(bh3));
                asm volatile("mma.sync.aligned.m16n8k16.row.col.f32.bf16.bf16.f32 "
                             "{%0,%1,%2,%3},{%4,%5,%6,%7},{%8,%9},{%0,%1,%2,%3};"
                             : "+f"(acc[n1][0]), "+f"(acc[n1][1]), "+f"(acc[n1][2]), "+f"(acc[n1][3])
                             : "r"(ah0), "r"(ah1), "r"(ah2), "r"(ah3), "r"(bl2), "r"(bl3));
            }
        }
        __syncthreads();
    }

    // ---- epilogue ----
    int gr0 = r0 + wid * 16 + (lane >> 2);
    int gr1 = gr0 + 8;

    if (EPI == 2) {
        int gmin = g_nodeg[r0 < nrows ? r0 : nrows - 1];
        int glast = g_nodeg[min(r0 + 127, nrows - 1)];
        int g0 = (gr0 < nrows) ? g_nodeg[gr0] : -1;
        int g1 = (gr1 < nrows) ? g_nodeg[gr1] : -1;
        int i0 = g0 - gmin, i1 = g1 - gmin;
#pragma unroll
        for (int n = 0; n < NT; n++) {
            int col = col0 + n * 8 + (lane & 3) * 2;
            float b0 = bias[col], b1 = bias[col + 1];
            float v0 = fmaxf(acc[n][0] + b0, 0.f);
            float v1 = fmaxf(acc[n][1] + b1, 0.f);
            float v2 = fmaxf(acc[n][2] + b0, 0.f);
            float v3 = fmaxf(acc[n][3] + b1, 0.f);
            if (g0 >= 0) {
                if ((unsigned)i0 < 32u) {
                    atomicMax(&sPool[i0 * 128 + col],     __float_as_int(v0));
                    atomicMax(&sPool[i0 * 128 + col + 1], __float_as_int(v1));
                } else {
                    atomicMax(&g_pool[g0 * 128 + col],     __float_as_int(v0));
                    atomicMax(&g_pool[g0 * 128 + col + 1], __float_as_int(v1));
                }
            }
            if (g1 >= 0) {
                if ((unsigned)i1 < 32u) {
                    atomicMax(&sPool[i1 * 128 + col],     __float_as_int(v2));
                    atomicMax(&sPool[i1 * 128 + col + 1], __float_as_int(v3));
                } else {
                    atomicMax(&g_pool[g1 * 128 + col],     __float_as_int(v2));
                    atomicMax(&g_pool[g1 * 128 + col + 1], __float_as_int(v3));
                }
            }
        }
        __syncthreads();
        int span = min(glast - gmin, 31);
        int total = (span + 1) * 128;
        for (int i = tid; i < total; i += 256) {
            int b = sPool[i];
            if (b != 0)
                atomicMax(&g_pool[(gmin + i / 128) * 128 + (i & 127)], b);
        }
    } else {
#pragma unroll
        for (int n = 0; n < NT; n++) {
            int col = col0 + n * 8 + (lane & 3) * 2;
            float v0 = acc[n][0], v1 = acc[n][1], v2 = acc[n][2], v3 = acc[n][3];
            if (EPI >= 1) {
                float b0 = bias[col], b1 = bias[col + 1];
                v0 += b0; v1 += b1; v2 += b0; v3 += b1;
                if (EPI == 1) {
                    v0 = fmaxf(v0, 0.f); v1 = fmaxf(v1, 0.f);
                    v2 = fmaxf(v2, 0.f); v3 = fmaxf(v3, 0.f);
                }
            }
            if (gr0 < nrows) *(float2*)&Y[(size_t)gr0 * ldy + col] = make_float2(v0, v1);
            if (gr1 < nrows) *(float2*)&Y[(size_t)gr1 * ldy + col] = make_float2(v2, v3);
        }
    }
}

// ---------------- CSR gather (pipelined edge prefetch): O = P @ H --------
template<int C, bool EPI>
__global__ __launch_bounds__(256)
void gather_kernel(const float* __restrict__ H, float* __restrict__ O,
                   const float* __restrict__ bias) {
    constexpr int L = C / 4;
    int idx = blockIdx.x * 256 + threadIdx.x;
    int node = idx / L;
    int c4 = (idx % L) * 4;
    if (node >= NN) return;
    int s = g_rowptr[node], e = g_rowptr[node + 1];
    float ax = 0.f, ay = 0.f, az = 0.f, aw = 0.f;
    float2 ew = (s < e) ? g_csr2[s] : make_float2(0.f, 0.f);
    for (int k = s; k < e; k++) {
        float2 cur = ew;
        if (k + 1 < e) ew = g_csr2[k + 1];     // prefetch: overlaps H load below
        int src = __float_as_int(cur.x);
        float w = cur.y;
        float4 h = *(const float4*)&H[(size_t)src * C + c4];
        ax += h.x * w; ay += h.y * w; az += h.z * w; aw += h.w * w;
    }
    float d = g_dis[node];
    float d2 = d * d;
    float4 hn = *(const float4*)&H[(size_t)node * C + c4];
    float4 o;
    o.x = d * ax + hn.x * d2;
    o.y = d * ay + hn.y * d2;
    o.z = d * az + hn.z * d2;
    o.w = d * aw + hn.w * d2;
    if (EPI) {
        float4 b = *(const float4*)&bias[c4];
        o.x = fmaxf(o.x + b.x, 0.f);
        o.y = fmaxf(o.y + b.y, 0.f);
        o.z = fmaxf(o.z + b.z, 0.f);
        o.w = fmaxf(o.w + b.w, 0.f);
    }
    *(float4*)&O[(size_t)node * C + c4] = o;
}

// ---------------- launch ----------------
extern "C" void kernel_launch(void* const* d_in, const int* in_sizes, int n_in,
                              void* d_out, int out_size) {
    const float* x     = (const float*)d_in[0];
    const void*  ei    = d_in[1];
    const void*  batch = d_in[2];
    const float* nw    = (const float*)d_in[3];
    const float* nbi   = (const float*)d_in[4];
    const float* W1    = (const float*)d_in[5];
    const float* b1    = (const float*)d_in[6];
    const float* W2    = (const float*)d_in[7];
    const float* b2    = (const float*)d_in[8];
    const float* W3    = (const float*)d_in[9];
    const float* b3    = (const float*)d_in[10];
    const float* l1W   = (const float*)d_in[11];
    const float* l1b   = (const float*)d_in[12];
    const float* l2W   = (const float*)d_in[13];
    const float* l2b   = (const float*)d_in[14];
    float* out = (float*)d_out;

    void *pA, *pB, *pC, *pPool;
    cudaGetSymbolAddress(&pA, g_bufA);
    cudaGetSymbolAddress(&pB, g_bufB);
    cudaGetSymbolAddress(&pC, g_bufC);
    cudaGetSymbolAddress(&pPool, g_pool);
    float* fA = (float*)pA;
    float* fB = (float*)pB;
    float* fC = (float*)pC;
    const float* poolf = (const float*)pPool;   // bit-pattern of >=0 floats

    const int NB_SCAN = (NN + SCAN_B - 1) / SCAN_B;

    init_kernel<<<(GG * 128 + 255) / 256, 256>>>(ei, batch);
    graph_kernel<<<(EE + 255) / 256, 256>>>(batch, ei);

    scan1_kernel<<<NB_SCAN, SCAN_B>>>();
    scan2_kernel<<<1, SCAN_B>>>(NB_SCAN);
    scan3_kernel<<<(NN + 255) / 256, 256>>>();
    fill_kernel<<<(EE + 255) / 256, 256>>>(ei);

    stats_kernel<<<GG, 128>>>(x, nw, nbi);

    const int GB = (NN + 127) / 128;

    // layer 1: (norm ∘ x) @ W1 -> B(32ch); propagate w/ bias+relu -> A
    mma_gemm<128, 32, true, 0><<<GB, 256>>>(x, W1, 32, nullptr, fB, 32, NN);
    gather_kernel<32, true><<<(NN * 8 + 255) / 256, 256>>>(fB, fA, b1);

    // layer 2: propagate (32ch) -> C; GEMM 32->64 w/ bias+relu -> B
    gather_kernel<32, false><<<(NN * 8 + 255) / 256, 256>>>(fA, fC, nullptr);
    mma_gemm<32, 64, false, 1><<<GB, 256>>>(fC, W2, 64, b2, fB, 64, NN);

    // layer 3: propagate (64ch) -> A; GEMM 64->128 + bias+relu + FUSED pool
    gather_kernel<64, false><<<(NN * 16 + 255) / 256, 256>>>(fB, fA, nullptr);
    mma_gemm<64, 128, false, 2><<<GB, 256>>>(fA, W3, 128, b3, nullptr, 128, NN);

    // head: pooled[G,128] @ l1W (+relu) -> B[G,256]; @ l2W (+bias) -> out
    {
        dim3 grid1((GG + 127) / 128, 4);
        mma_gemm<128, 64, false, 1><<<grid1, 256>>>(poolf, l1W, 256, l1b, fB, 256, GG);
        dim3 grid2((GG + 127) / 128, 2);
        mma_gemm<256, 64, false, 3><<<grid2, 256>>>(fB, l2W, 128, l2b, out, 128, GG);
    }
}

// round 14
// speedup vs baseline: 1.0714x; 1.0714x over previous
#include <cuda_runtime.h>
#include <cuda_bf16.h>
#include <cstdint>
#include <cstddef>

#define NN   200000
#define EE   800000
#define FIN  128
#define GG   8000
#define SCAN_B 512

// ---------------- device scratch ----------------
__device__ float g_bufA[(size_t)NN * 128];
__device__ float g_bufB[(size_t)NN * 128];
__device__ float g_bufC[(size_t)NN * 128];
__device__ float g_dis[NN];
__device__ int   g_cnt[NN];
__device__ int   g_rowptr[NN + 1];
__device__ int   g_fill[NN];
__device__ float2 g_csr2[EE];          // packed {src_bits, dis[src]}
__device__ int   g_bsum[SCAN_B];
__device__ int   g_boff[SCAN_B];
__device__ int   g_gptr[GG + 1];
__device__ int   g_nodeg[NN];
__device__ float g_na[GG * 128];
__device__ float g_nb[GG * 128];
__device__ int   g_pool[GG * 128];     // float bits; post-relu >= 0 so int max == float max
__device__ int   g_ei64;
__device__ int   g_b64;

__device__ __forceinline__ long long ld_idx(const void* p, long long i, int is64) {
    if (is64) return ((const long long*)p)[i];
    return (long long)((const int*)p)[i];
}

// ---------------- init (cnt + pool) + dtype detection (block 0) ----------
__global__ void init_kernel(const void* ei, const void* batch) {
    int i = blockIdx.x * blockDim.x + threadIdx.x;
    if (i < NN) g_cnt[i] = 0;
    if (i < GG * 128) g_pool[i] = 0;
    if (blockIdx.x == 0 && threadIdx.x < 32) {
        int lane = threadIdx.x;
        long long v = ((const long long*)ei)[lane];
        unsigned bad1 = __ballot_sync(0xffffffffu, v < 0 || v >= NN);
        long long q = ((const long long*)batch)[lane];
        unsigned bad2 = __ballot_sync(0xffffffffu, q < 0 || q >= GG);
        if (lane == 0) {
            g_ei64 = (bad1 == 0u);
            g_b64  = (bad2 == 0u);
        }
    }
}

// ---------------- batchinfo (nodeg + gptr) + degree count, merged --------
__global__ void graph_kernel(const void* __restrict__ batch,
                             const void* __restrict__ ei) {
    int i = blockIdx.x * blockDim.x + threadIdx.x;
    if (i < NN) {
        int is64 = g_b64;
        int bi = (int)ld_idx(batch, i, is64);
        g_nodeg[i] = bi;
        if (i == 0) {
            for (int g = 0; g <= bi; g++) g_gptr[g] = 0;
        } else {
            int bp = (int)ld_idx(batch, i - 1, is64);
            for (int g = bp + 1; g <= bi; g++) g_gptr[g] = i;
        }
        if (i == NN - 1) {
            for (int g = bi + 1; g <= GG; g++) g_gptr[g] = NN;
        }
    }
    if (i < EE) {
        int dst = (int)ld_idx(ei, (long long)EE + i, g_ei64);
        atomicAdd(&g_cnt[dst], 1);
    }
}

// ---------------- exclusive scan of g_cnt -> g_rowptr (+ dis fused) ------
__global__ void scan1_kernel() {
    __shared__ int s[SCAN_B];
    int tid = threadIdx.x;
    int i = blockIdx.x * SCAN_B + tid;
    int v = (i < NN) ? g_cnt[i] : 0;
    if (i < NN) g_dis[i] = rsqrtf(1.0f + (float)v);
    s[tid] = v;
    __syncthreads();
    for (int off = 1; off < SCAN_B; off <<= 1) {
        int t = (tid >= off) ? s[tid - off] : 0;
        __syncthreads();
        s[tid] += t;
        __syncthreads();
    }
    if (i < NN) g_rowptr[i] = s[tid] - v;
    if (tid == SCAN_B - 1) g_bsum[blockIdx.x] = s[tid];
}
__global__ void scan2_kernel(int nb) {
    __shared__ int s[SCAN_B];
    int tid = threadIdx.x;
    int v = (tid < nb) ? g_bsum[tid] : 0;
    s[tid] = v;
    __syncthreads();
    for (int off = 1; off < SCAN_B; off <<= 1) {
        int t = (tid >= off) ? s[tid - off] : 0;
        __syncthreads();
        s[tid] += t;
        __syncthreads();
    }
    g_boff[tid] = s[tid] - v;
}
__global__ void scan3_kernel() {
    int i = blockIdx.x * blockDim.x + threadIdx.x;
    if (i < NN) {
        int v = g_rowptr[i] + g_boff[i / SCAN_B];
        g_rowptr[i] = v;
        g_fill[i] = v;
    }
    if (i == 0) g_rowptr[NN] = EE;
}

// ---------------- CSR fill (packed) ----------------
__global__ void fill_kernel(const void* __restrict__ ei) {
    int i = blockIdx.x * blockDim.x + threadIdx.x;
    if (i >= EE) return;
    int is64 = g_ei64;
    int src = (int)ld_idx(ei, i, is64);
    int dst = (int)ld_idx(ei, (long long)EE + i, is64);
    int pos = atomicAdd(&g_fill[dst], 1);
    g_csr2[pos] = make_float2(__int_as_float(src), g_dis[src]);
}

// ---------------- instance norm stats -> affine (v*na + nb) --------------
__global__ void stats_kernel(const float* __restrict__ x,
                             const float* __restrict__ wp,
                             const float* __restrict__ bp) {
    int g = blockIdx.x;
    int c = threadIdx.x;   // 128
    int s = g_gptr[g], e = g_gptr[g + 1];
    if (s >= e) { g_na[g * 128 + c] = 0.f; g_nb[g * 128 + c] = 0.f; return; }
    float w = wp[0], b = bp[0];
    float sum = 0.f, sq = 0.f;
    for (int i = s; i < e; i++) {
        float v = x[(size_t)i * FIN + c];
        sum += v; sq += v * v;
    }
    float cnt  = (float)(e - s);
    float mean = sum / cnt;
    float var  = sq / cnt - mean * mean;
    float inv  = rsqrtf(var + 1e-5f);
    float na = inv * w;
    g_na[g * 128 + c] = na;
    g_nb[g * 128 + c] = b - mean * na;
}

// ---------------- bf16x3 split tensor-core GEMM (pipelined X stage) ------
// Y[r, col0+c] = sum_k X[r,k] * W[k, col0+c]   (only lo*lo dropped)
// 256 threads / 8 warps, 128 rows per block; warp w -> rows [w*16, w*16+16).
// X chunk k+1 is prefetched into registers during chunk k's mma phase.
// KCH: k-chunk size (32 or 64).  EPI: 0 plain, 1 bias+relu,
// 2 bias+relu + fused per-graph max-pool (NO Y), 3 bias only.
// NORM: fuse instnorm affine (CIN must be 128).
template<int CIN, int COUT, int KCH, bool NORM, int EPI>
__global__ __launch_bounds__(256, 2)
void mma_gemm(const float* __restrict__ X, const float* __restrict__ W,
              int ldw, const float* __restrict__ bias,
              float* __restrict__ Y, int ldy, int nrows) {
    constexpr int ST  = KCH + 8;         // padded stride (bf16)
    constexpr int NT  = COUT / 8;        // n-tiles (even)
    constexpr int PSLOT = (EPI == 2) ? 32 : 1;
    constexpr int KQ  = KCH / 4;         // float4 per row
    constexpr int XJ  = 128 * KQ / 256;  // float4 per thread per chunk

    __shared__ __align__(16) __nv_bfloat16 sXhi[128 * ST];
    __shared__ __align__(16) __nv_bfloat16 sXlo[128 * ST];
    __shared__ __align__(16) __nv_bfloat16 sWhi[COUT * ST];
    __shared__ __align__(16) __nv_bfloat16 sWlo[COUT * ST];
    __shared__ int sPool[PSLOT * 128];

    int tid = threadIdx.x;
    int wid = tid >> 5;
    int lane = tid & 31;
    int r0 = blockIdx.x * 128;
    int col0 = blockIdx.y * COUT;

    if (EPI == 2) {
        for (int i = tid; i < PSLOT * 128; i += 256) sPool[i] = 0;
    }

    float acc[NT][4];
#pragma unroll
    for (int n = 0; n < NT; n++)
#pragma unroll
        for (int j = 0; j < 4; j++) acc[n][j] = 0.f;

    // ldmatrix base addresses
    int arow = lane & 15;
    int akoff = (lane >> 4) * 8;
    unsigned aAhi = (unsigned)__cvta_generic_to_shared(
        &sXhi[(wid * 16 + arow) * ST + akoff]);
    unsigned aAlo = (unsigned)__cvta_generic_to_shared(
        &sXlo[(wid * 16 + arow) * ST + akoff]);
    // B paired x4: tiles n, n+1 in one ldmatrix
    int brow = (lane & 7) + (lane >> 4) * 8;
    int bkoff = ((lane >> 3) & 1) * 8;
    unsigned aBhi = (unsigned)__cvta_generic_to_shared(&sWhi[brow * ST + bkoff]);
    unsigned aBlo = (unsigned)__cvta_generic_to_shared(&sWlo[brow * ST + bkoff]);

    // X prefetch registers (chunk-invariant per-thread tile coords)
    float4 xp[XJ];
    int xr_rl[XJ], xr_kq[XJ];
#pragma unroll
    for (int j = 0; j < XJ; j++) {
        int i = tid + j * 256;
        xr_rl[j] = i / KQ;
        xr_kq[j] = i % KQ;
    }

    // prefetch chunk 0
#pragma unroll
    for (int j = 0; j < XJ; j++) {
        int row = r0 + xr_rl[j];
        xp[j] = (row < nrows)
            ? *(const float4*)&X[(size_t)row * CIN + xr_kq[j] * 4]
            : make_float4(0.f, 0.f, 0.f, 0.f);
    }

    for (int k0 = 0; k0 < CIN; k0 += KCH) {
        // ---- store prefetched X chunk: norm + split -> smem ----
#pragma unroll
        for (int j = 0; j < XJ; j++) {
            float4 v = xp[j];
            if (NORM) {
                int row = r0 + xr_rl[j];
                if (row < nrows) {
                    int g = g_nodeg[row];
                    const float4 na = *(const float4*)&g_na[g * 128 + k0 + xr_kq[j] * 4];
                    const float4 nb = *(const float4*)&g_nb[g * 128 + k0 + xr_kq[j] * 4];
                    v.x = v.x * na.x + nb.x; v.y = v.y * na.y + nb.y;
                    v.z = v.z * na.z + nb.z; v.w = v.w * na.w + nb.w;
                }
            }
            __nv_bfloat162 h01 = __floats2bfloat162_rn(v.x, v.y);
            __nv_bfloat162 h23 = __floats2bfloat162_rn(v.z, v.w);
            __nv_bfloat162 l01 = __floats2bfloat162_rn(
                v.x - __bfloat162float(h01.x), v.y - __bfloat162float(h01.y));
            __nv_bfloat162 l23 = __floats2bfloat162_rn(
                v.z - __bfloat162float(h23.x), v.w - __bfloat162float(h23.y));
            int base = xr_rl[j] * ST + xr_kq[j] * 4;
            uint2 hu, lu;
            hu.x = *(unsigned*)&h01; hu.y = *(unsigned*)&h23;
            lu.x = *(unsigned*)&l01; lu.y = *(unsigned*)&l23;
            *(uint2*)&sXhi[base] = hu;
            *(uint2*)&sXlo[base] = lu;
        }
        // ---- W chunk: [k][c] -> Wt [c][k], coalesced loads, bf162 stores ----
        for (int i = tid; i < COUT * (KCH / 2); i += 256) {
            int c  = i % COUT;
            int kp = i / COUT;
            int k  = kp * 2;
            float w0 = W[(size_t)(k0 + k)     * ldw + col0 + c];
            float w1 = W[(size_t)(k0 + k + 1) * ldw + col0 + c];
            __nv_bfloat162 h = __floats2bfloat162_rn(w0, w1);
            __nv_bfloat162 l = __floats2bfloat162_rn(
                w0 - __bfloat162float(h.x), w1 - __bfloat162float(h.y));
            *(__nv_bfloat162*)&sWhi[c * ST + k] = h;
            *(__nv_bfloat162*)&sWlo[c * ST + k] = l;
        }
        __syncthreads();

        // ---- prefetch next X chunk (overlaps with mma phase) ----
        if (k0 + KCH < CIN) {
#pragma unroll
            for (int j = 0; j < XJ; j++) {
                int row = r0 + xr_rl[j];
                xp[j] = (row < nrows)
                    ? *(const float4*)&X[(size_t)row * CIN + k0 + KCH + xr_kq[j] * 4]
                    : make_float4(0.f, 0.f, 0.f, 0.f);
            }
        }

#pragma unroll
        for (int ks = 0; ks < KCH / 16; ks++) {
            unsigned ah0, ah1, ah2, ah3, al0, al1, al2, al3;
            asm volatile("ldmatrix.sync.aligned.m8n8.x4.shared.b16 {%0,%1,%2,%3}, [%4];"
                         : "=r"(ah0), "=r"(ah1), "=r"(ah2), "=r"(ah3)
                         : "r"(aAhi + ks * 32u));
            asm volatile("ldmatrix.sync.aligned.m8n8.x4.shared.b16 {%0,%1,%2,%3}, [%4];"
                         : "=r"(al0), "=r"(al1), "=r"(al2), "=r"(al3)
                         : "r"(aAlo + ks * 32u));
#pragma unroll
            for (int np = 0; np < NT / 2; np++) {
                unsigned bh0, bh1, bh2, bh3, bl0, bl1, bl2, bl3;
                unsigned boff = (unsigned)(np * 16 * ST * 2) + ks * 32u;
                asm volatile("ldmatrix.sync.aligned.m8n8.x4.shared.b16 {%0,%1,%2,%3}, [%4];"
                             : "=r"(bh0), "=r"(bh1), "=r"(bh2), "=r"(bh3)
                             : "r"(aBhi + boff));
                asm volatile("ldmatrix.sync.aligned.m8n8.x4.shared.b16 {%0,%1,%2,%3}, [%4];"
                             : "=r"(bl0), "=r"(bl1), "=r"(bl2), "=r"(bl3)
                             : "r"(aBlo + boff));
                int n0 = np * 2, n1 = np * 2 + 1;
                asm volatile("mma.sync.aligned.m16n8k16.row.col.f32.bf16.bf16.f32 "
                             "{%0,%1,%2,%3},{%4,%5,%6,%7},{%8,%9},{%0,%1,%2,%3};"
                             : "+f"(acc[n0][0]), "+f"(acc[n0][1]), "+f"(acc[n0][2]), "+f"(acc[n0][3])
                             : "r"(ah0), "r"(ah1), "r"(ah2), "r"(ah3), "r"(bh0), "r"(bh1));
                asm volatile("mma.sync.aligned.m16n8k16.row.col.f32.bf16.bf16.f32 "
                             "{%0,%1,%2,%3},{%4,%5,%6,%7},{%8,%9},{%0,%1,%2,%3};"
                             : "+f"(acc[n0][0]), "+f"(acc[n0][1]), "+f"(acc[n0][2]), "+f"(acc[n0][3])
                             : "r"(al0), "r"(al1), "r"(al2), "r"(al3), "r"(bh0), "r"(bh1));
                asm volatile("mma.sync.aligned.m16n8k16.row.col.f32.bf16.bf16.f32 "
                             "{%0,%1,%2,%3},{%4,%5,%6,%7},{%8,%9},{%0,%1,%2,%3};"
                             : "+f"(acc[n0][0]), "+f"(acc[n0][1]), "+f"(acc[n0][2]), "+f"(acc[n0][3])
                             : "r"(ah0), "r"(ah1), "r"(ah2), "r"(ah3), "r"(bl0), "r"(bl1));
                asm volatile("mma.sync.aligned.m16n8k16.row.col.f32.bf16.bf16.f32 "
                             "{%0,%1,%2,%3},{%4,%5,%6,%7},{%8,%9},{%0,%1,%2,%3};"
                             : "+f"(acc[n1][0]), "+f"(acc[n1][1]), "+f"(acc[n1][2]), "+f"(acc[n1][3])
                             : "r"(ah0), "r"(ah1), "r"(ah2), "r"(ah3), "r"(bh2), "r"(bh3));
                asm volatile("mma.sync.aligned.m16n8k16.row.col.f32.bf16.bf16.f32 "
                             "{%0,%1,%2,%3},{%4,%5,%6,%7},{%8,%9},{%0,%1,%2,%3};"
                             : "+f"(acc[n1][0]), "+f"(acc[n1][1]), "+f"(acc[n1][2]), "+f"(acc[n1][3])
                             : "r"(al0), "r"(al1), "r"(al2), "r"(al3), "r"(bh2), "r"(bh3));
                asm volatile("mma.sync.aligned.m16n8k16.row.col.f32.bf16.bf16.f32 "
                             "{%0,%1,%2,%3},{%4,%5,%6,%7},{%8,%9},{%0,%1,%2,%3};"
                             : "+f"(acc[n1][0]), "+f"(acc[n1][1]), "+f"(acc[n1][2]), "+f"(acc[n1][3])
                             : "r"(ah0), "r"(ah1), "r"(ah2), "r"(ah3), "r"(bl2), "r"(bl3));
            }
        }
        __syncthreads();
    }

    // ---- epilogue ----
    int gr0 = r0 + wid * 16 + (lane >> 2);
    int gr1 = gr0 + 8;

    if (EPI == 2) {
        int gmin = g_nodeg[r0 < nrows ? r0 : nrows - 1];
        int glast = g_nodeg[min(r0 + 127, nrows - 1)];
        int g0 = (gr0 < nrows) ? g_nodeg[gr0] : -1;
        int g1 = (gr1 < nrows) ? g_nodeg[gr1] : -1;
        int i0 = g0 - gmin, i1 = g1 - gmin;
#pragma unroll
        for (int n = 0; n < NT; n++) {
            int col = col0 + n * 8 + (lane & 3) * 2;
            float b0 = bias[col], b1 = bias[col + 1];
            float v0 = fmaxf(acc[n][0] + b0, 0.f);
            float v1 = fmaxf(acc[n][1] + b1, 0.f);
            float v2 = fmaxf(acc[n][2] + b0, 0.f);
            float v3 = fmaxf(acc[n][3] + b1, 0.f);
            if (g0 >= 0) {
                if ((unsigned)i0 < 32u) {
                    atomicMax(&sPool[i0 * 128 + col],     __float_as_int(v0));
                    atomicMax(&sPool[i0 * 128 + col + 1], __float_as_int(v1));
                } else {
                    atomicMax(&g_pool[g0 * 128 + col],     __float_as_int(v0));
                    atomicMax(&g_pool[g0 * 128 + col + 1], __float_as_int(v1));
                }
            }
            if (g1 >= 0) {
                if ((unsigned)i1 < 32u) {
                    atomicMax(&sPool[i1 * 128 + col],     __float_as_int(v2));
                    atomicMax(&sPool[i1 * 128 + col + 1], __float_as_int(v3));
                } else {
                    atomicMax(&g_pool[g1 * 128 + col],     __float_as_int(v2));
                    atomicMax(&g_pool[g1 * 128 + col + 1], __float_as_int(v3));
                }
            }
        }
        __syncthreads();
        int span = min(glast - gmin, 31);
        int total = (span + 1) * 128;
        for (int i = tid; i < total; i += 256) {
            int b = sPool[i];
            if (b != 0)
                atomicMax(&g_pool[(gmin + i / 128) * 128 + (i & 127)], b);
        }
    } else {
#pragma unroll
        for (int n = 0; n < NT; n++) {
            int col = col0 + n * 8 + (lane & 3) * 2;
            float v0 = acc[n][0], v1 = acc[n][1], v2 = acc[n][2], v3 = acc[n][3];
            if (EPI >= 1) {
                float b0 = bias[col], b1 = bias[col + 1];
                v0 += b0; v1 += b1; v2 += b0; v3 += b1;
                if (EPI == 1) {
                    v0 = fmaxf(v0, 0.f); v1 = fmaxf(v1, 0.f);
                    v2 = fmaxf(v2, 0.f); v3 = fmaxf(v3, 0.f);
                }
            }
            if (gr0 < nrows) *(float2*)&Y[(size_t)gr0 * ldy + col] = make_float2(v0, v1);
            if (gr1 < nrows) *(float2*)&Y[(size_t)gr1 * ldy + col] = make_float2(v2, v3);
        }
    }
}

// ---------------- CSR gather (vectorized): O = P @ H ---------------------
template<int C, bool EPI>
__global__ __launch_bounds__(256)
void gather_kernel(const float* __restrict__ H, float* __restrict__ O,
                   const float* __restrict__ bias) {
    constexpr int L = C / 4;
    int idx = blockIdx.x * 256 + threadIdx.x;
    int node = idx / L;
    int c4 = (idx % L) * 4;
    if (node >= NN) return;
    int s = g_rowptr[node], e = g_rowptr[node + 1];
    float ax = 0.f, ay = 0.f, az = 0.f, aw = 0.f;
    for (int k = s; k < e; k++) {
        float2 ew = g_csr2[k];
        int src = __float_as_int(ew.x);
        float w = ew.y;
        float4 h = *(const float4*)&H[(size_t)src * C + c4];
        ax += h.x * w; ay += h.y * w; az += h.z * w; aw += h.w * w;
    }
    float d = g_dis[node];
    float d2 = d * d;
    float4 hn = *(const float4*)&H[(size_t)node * C + c4];
    float4 o;
    o.x = d * ax + hn.x * d2;
    o.y = d * ay + hn.y * d2;
    o.z = d * az + hn.z * d2;
    o.w = d * aw + hn.w * d2;
    if (EPI) {
        float4 b = *(const float4*)&bias[c4];
        o.x = fmaxf(o.x + b.x, 0.f);
        o.y = fmaxf(o.y + b.y, 0.f);
        o.z = fmaxf(o.z + b.z, 0.f);
        o.w = fmaxf(o.w + b.w, 0.f);
    }
    *(float4*)&O[(size_t)node * C + c4] = o;
}

// ---------------- launch ----------------
extern "C" void kernel_launch(void* const* d_in, const int* in_sizes, int n_in,
                              void* d_out, int out_size) {
    const float* x     = (const float*)d_in[0];
    const void*  ei    = d_in[1];
    const void*  batch = d_in[2];
    const float* nw    = (const float*)d_in[3];
    const float* nbi   = (const float*)d_in[4];
    const float* W1    = (const float*)d_in[5];
    const float* b1    = (const float*)d_in[6];
    const float* W2    = (const float*)d_in[7];
    const float* b2    = (const float*)d_in[8];
    const float* W3    = (const float*)d_in[9];
    const float* b3    = (const float*)d_in[10];
    const float* l1W   = (const float*)d_in[11];
    const float* l1b   = (const float*)d_in[12];
    const float* l2W   = (const float*)d_in[13];
    const float* l2b   = (const float*)d_in[14];
    float* out = (float*)d_out;

    void *pA, *pB, *pC, *pPool;
    cudaGetSymbolAddress(&pA, g_bufA);
    cudaGetSymbolAddress(&pB, g_bufB);
    cudaGetSymbolAddress(&pC, g_bufC);
    cudaGetSymbolAddress(&pPool, g_pool);
    float* fA = (float*)pA;
    float* fB = (float*)pB;
    float* fC = (float*)pC;
    const float* poolf = (const float*)pPool;   // bit-pattern of >=0 floats

    const int NB_SCAN = (NN + SCAN_B - 1) / SCAN_B;

    init_kernel<<<(GG * 128 + 255) / 256, 256>>>(ei, batch);
    graph_kernel<<<(EE + 255) / 256, 256>>>(batch, ei);

    scan1_kernel<<<NB_SCAN, SCAN_B>>>();
    scan2_kernel<<<1, SCAN_B>>>(NB_SCAN);
    scan3_kernel<<<(NN + 255) / 256, 256>>>();
    fill_kernel<<<(EE + 255) / 256, 256>>>(ei);

    stats_kernel<<<GG, 128>>>(x, nw, nbi);

    const int GB = (NN + 127) / 128;

    // layer 1: (norm ∘ x) @ W1 -> B(32ch); propagate w/ bias+relu -> A
    mma_gemm<128, 32, 64, true, 0><<<GB, 256>>>(x, W1, 32, nullptr, fB, 32, NN);
    gather_kernel<32, true><<<(NN * 8 + 255) / 256, 256>>>(fB, fA, b1);

    // layer 2: propagate (32ch) -> C; GEMM 32->64 w/ bias+relu -> B
    gather_kernel<32, false><<<(NN * 8 + 255) / 256, 256>>>(fA, fC, nullptr);
    mma_gemm<32, 64, 32, false, 1><<<GB, 256>>>(fC, W2, 64, b2, fB, 64, NN);

    // layer 3: propagate (64ch) -> A; GEMM 64->128 + bias+relu + FUSED pool
    gather_kernel<64, false><<<(NN * 16 + 255) / 256, 256>>>(fB, fA, nullptr);
    mma_gemm<64, 128, 32, false, 2><<<GB, 256>>>(fA, W3, 128, b3, nullptr, 128, NN);

    // head: pooled[G,128] @ l1W (+relu) -> B[G,256]; @ l2W (+bias) -> out
    {
        dim3 grid1((GG + 127) / 128, 4);
        mma_gemm<128, 64, 32, false, 1><<<grid1, 256>>>(poolf, l1W, 256, l1b, fB, 256, GG);
        dim3 grid2((GG + 127) / 128, 2);
        mma_gemm<256, 64, 64, false, 3><<<grid2, 256>>>(fB, l2W, 128, l2b, out, 128, GG);
    }
}

// round 15
// speedup vs baseline: 1.0887x; 1.0162x over previous
#include <cuda_runtime.h>
#include <cuda_bf16.h>
#include <cstdint>
#include <cstddef>

#define NN   200000
#define EE   800000
#define FIN  128
#define GG   8000
#define SCAN_B 512
#define NBS  ((NN + SCAN_B - 1) / SCAN_B)   // 391

// ---------------- device scratch ----------------
__device__ float g_bufA[(size_t)NN * 128];
__device__ float g_bufB[(size_t)NN * 128];
__device__ float g_bufC[(size_t)NN * 128];
__device__ float g_dis[NN];
__device__ int   g_cnt[NN];
__device__ int   g_rowptr[NN + 1];
__device__ int   g_fill[NN];
__device__ float2 g_csr2[EE];          // packed {src_bits, dis[src]}
__device__ int   g_bsum[NBS];
__device__ int   g_gptr[GG + 1];
__device__ int   g_nodeg[NN];
__device__ float g_na[GG * 128];
__device__ float g_nb[GG * 128];
__device__ int   g_pool[GG * 128];     // float bits; post-relu >= 0 so int max == float max
__device__ int   g_ei64;
__device__ int   g_b64;

__device__ __forceinline__ long long ld_idx(const void* p, long long i, int is64) {
    if (is64) return ((const long long*)p)[i];
    return (long long)((const int*)p)[i];
}

// ---------------- init (cnt + pool) + dtype detection (block 0) ----------
__global__ void init_kernel(const void* ei, const void* batch) {
    int i = blockIdx.x * blockDim.x + threadIdx.x;
    if (i < NN) g_cnt[i] = 0;
    if (i < GG * 128) g_pool[i] = 0;
    if (blockIdx.x == 0 && threadIdx.x < 32) {
        int lane = threadIdx.x;
        long long v = ((const long long*)ei)[lane];
        unsigned bad1 = __ballot_sync(0xffffffffu, v < 0 || v >= NN);
        long long q = ((const long long*)batch)[lane];
        unsigned bad2 = __ballot_sync(0xffffffffu, q < 0 || q >= GG);
        if (lane == 0) {
            g_ei64 = (bad1 == 0u);
            g_b64  = (bad2 == 0u);
        }
    }
}

// ---------------- batchinfo (nodeg + gptr) + degree count, merged --------
__global__ void graph_kernel(const void* __restrict__ batch,
                             const void* __restrict__ ei) {
    int i = blockIdx.x * blockDim.x + threadIdx.x;
    if (i < NN) {
        int is64 = g_b64;
        int bi = (int)ld_idx(batch, i, is64);
        g_nodeg[i] = bi;
        if (i == 0) {
            for (int g = 0; g <= bi; g++) g_gptr[g] = 0;
        } else {
            int bp = (int)ld_idx(batch, i - 1, is64);
            for (int g = bp + 1; g <= bi; g++) g_gptr[g] = i;
        }
        if (i == NN - 1) {
            for (int g = bi + 1; g <= GG; g++) g_gptr[g] = NN;
        }
    }
    if (i < EE) {
        int dst = (int)ld_idx(ei, (long long)EE + i, g_ei64);
        atomicAdd(&g_cnt[dst], 1);
    }
}

// ---------------- scan stage 1: per-block scan + block sums (+ dis) ------
__global__ void scan1_kernel() {
    __shared__ int s[SCAN_B];
    int tid = threadIdx.x;
    int i = blockIdx.x * SCAN_B + tid;
    int v = (i < NN) ? g_cnt[i] : 0;
    if (i < NN) g_dis[i] = rsqrtf(1.0f + (float)v);
    s[tid] = v;
    __syncthreads();
    for (int off = 1; off < SCAN_B; off <<= 1) {
        int t = (tid >= off) ? s[tid - off] : 0;
        __syncthreads();
        s[tid] += t;
        __syncthreads();
    }
    if (i < NN) g_rowptr[i] = s[tid] - v;
    if (tid == SCAN_B - 1) g_bsum[blockIdx.x] = s[tid];
}

// ---------------- scan stage 2: add block offset (computed in-block) -----
// A 256-node block never crosses a 512-node scan-block boundary, so the
// whole block shares ONE offset = sum(g_bsum[0..sb0-1]), reduced in parallel.
__global__ void scan3_kernel() {
    __shared__ int sred[256];
    int tid = threadIdx.x;
    int base = blockIdx.x * 256;
    int sb0 = base / SCAN_B;
    int v = 0;
    for (int j = tid; j < sb0; j += 256) v += g_bsum[j];
    sred[tid] = v;
    __syncthreads();
    for (int off = 128; off > 0; off >>= 1) {
        if (tid < off) sred[tid] += sred[tid + off];
        __syncthreads();
    }
    int boff = sred[0];
    int i = base + tid;
    if (i < NN) {
        int vv = g_rowptr[i] + boff;
        g_rowptr[i] = vv;
        g_fill[i] = vv;
    }
    if (i == 0) g_rowptr[NN] = EE;
}

// ---------------- CSR fill (packed) ----------------
__global__ void fill_kernel(const void* __restrict__ ei) {
    int i = blockIdx.x * blockDim.x + threadIdx.x;
    if (i >= EE) return;
    int is64 = g_ei64;
    int src = (int)ld_idx(ei, i, is64);
    int dst = (int)ld_idx(ei, (long long)EE + i, is64);
    int pos = atomicAdd(&g_fill[dst], 1);
    g_csr2[pos] = make_float2(__int_as_float(src), g_dis[src]);
}

// ---------------- instance norm stats -> affine (v*na + nb) --------------
__global__ void stats_kernel(const float* __restrict__ x,
                             const float* __restrict__ wp,
                             const float* __restrict__ bp) {
    int g = blockIdx.x;
    int c = threadIdx.x;   // 128
    int s = g_gptr[g], e = g_gptr[g + 1];
    if (s >= e) { g_na[g * 128 + c] = 0.f; g_nb[g * 128 + c] = 0.f; return; }
    float w = wp[0], b = bp[0];
    float sum = 0.f, sq = 0.f;
    for (int i = s; i < e; i++) {
        float v = x[(size_t)i * FIN + c];
        sum += v; sq += v * v;
    }
    float cnt  = (float)(e - s);
    float mean = sum / cnt;
    float var  = sq / cnt - mean * mean;
    float inv  = rsqrtf(var + 1e-5f);
    float na = inv * w;
    g_na[g * 128 + c] = na;
    g_nb[g * 128 + c] = b - mean * na;
}

// ---------------- bf16x3 split tensor-core GEMM (pipelined X stage) ------
// Y[r, col0+c] = sum_k X[r,k] * W[k, col0+c]   (only lo*lo dropped)
// 256 threads / 8 warps, 128 rows per block; warp w -> rows [w*16, w*16+16).
// X chunk k+1 is prefetched into registers during chunk k's mma phase.
// EPI: 0 plain, 1 bias+relu, 2 bias+relu + fused per-graph max-pool (NO Y),
//      3 bias only.  NORM: fuse instnorm affine (CIN must be 128).
template<int CIN, int COUT, bool NORM, int EPI>
__global__ __launch_bounds__(256, 2)
void mma_gemm(const float* __restrict__ X, const float* __restrict__ W,
              int ldw, const float* __restrict__ bias,
              float* __restrict__ Y, int ldy, int nrows) {
    constexpr int KCH = 32;
    constexpr int ST  = 40;              // padded stride (bf16), 80B rows
    constexpr int NT  = COUT / 8;        // n-tiles (even)
    constexpr int PSLOT = (EPI == 2) ? 32 : 1;
    constexpr int KQ  = KCH / 4;         // 8 float4 per row
    constexpr int XJ  = 128 * KQ / 256;  // 4 float4 per thread per chunk

    __shared__ __align__(16) __nv_bfloat16 sXhi[128 * ST];
    __shared__ __align__(16) __nv_bfloat16 sXlo[128 * ST];
    __shared__ __align__(16) __nv_bfloat16 sWhi[COUT * ST];
    __shared__ __align__(16) __nv_bfloat16 sWlo[COUT * ST];
    __shared__ int sPool[PSLOT * 128];

    int tid = threadIdx.x;
    int wid = tid >> 5;
    int lane = tid & 31;
    int r0 = blockIdx.x * 128;
    int col0 = blockIdx.y * COUT;

    if (EPI == 2) {
        for (int i = tid; i < PSLOT * 128; i += 256) sPool[i] = 0;
    }

    float acc[NT][4];
#pragma unroll
    for (int n = 0; n < NT; n++)
#pragma unroll
        for (int j = 0; j < 4; j++) acc[n][j] = 0.f;

    // ldmatrix base addresses
    int arow = lane & 15;
    int akoff = (lane >> 4) * 8;
    unsigned aAhi = (unsigned)__cvta_generic_to_shared(
        &sXhi[(wid * 16 + arow) * ST + akoff]);
    unsigned aAlo = (unsigned)__cvta_generic_to_shared(
        &sXlo[(wid * 16 + arow) * ST + akoff]);
    // B paired x4: tiles n, n+1 in one ldmatrix
    int brow = (lane & 7) + (lane >> 4) * 8;
    int bkoff = ((lane >> 3) & 1) * 8;
    unsigned aBhi = (unsigned)__cvta_generic_to_shared(&sWhi[brow * ST + bkoff]);
    unsigned aBlo = (unsigned)__cvta_generic_to_shared(&sWlo[brow * ST + bkoff]);

    // X prefetch registers (chunk-invariant per-thread tile coords)
    float4 xp[XJ];
    int xr_rl[XJ], xr_kq[XJ];
#pragma unroll
    for (int j = 0; j < XJ; j++) {
        int i = tid + j * 256;
        xr_rl[j] = i / KQ;
        xr_kq[j] = i % KQ;
    }

    // prefetch chunk 0
#pragma unroll
    for (int j = 0; j < XJ; j++) {
        int row = r0 + xr_rl[j];
        xp[j] = (row < nrows)
            ? *(const float4*)&X[(size_t)row * CIN + xr_kq[j] * 4]
            : make_float4(0.f, 0.f, 0.f, 0.f);
    }

    for (int k0 = 0; k0 < CIN; k0 += KCH) {
        // ---- store prefetched X chunk: norm + split -> smem ----
#pragma unroll
        for (int j = 0; j < XJ; j++) {
            float4 v = xp[j];
            if (NORM) {
                int row = r0 + xr_rl[j];
                if (row < nrows) {
                    int g = g_nodeg[row];
                    const float4 na = *(const float4*)&g_na[g * 128 + k0 + xr_kq[j] * 4];
                    const float4 nb = *(const float4*)&g_nb[g * 128 + k0 + xr_kq[j] * 4];
                    v.x = v.x * na.x + nb.x; v.y = v.y * na.y + nb.y;
                    v.z = v.z * na.z + nb.z; v.w = v.w * na.w + nb.w;
                }
            }
            __nv_bfloat162 h01 = __floats2bfloat162_rn(v.x, v.y);
            __nv_bfloat162 h23 = __floats2bfloat162_rn(v.z, v.w);
            __nv_bfloat162 l01 = __floats2bfloat162_rn(
                v.x - __bfloat162float(h01.x), v.y - __bfloat162float(h01.y));
            __nv_bfloat162 l23 = __floats2bfloat162_rn(
                v.z - __bfloat162float(h23.x), v.w - __bfloat162float(h23.y));
            int base = xr_rl[j] * ST + xr_kq[j] * 4;
            uint2 hu, lu;
            hu.x = *(unsigned*)&h01; hu.y = *(unsigned*)&h23;
            lu.x = *(unsigned*)&l01; lu.y = *(unsigned*)&l23;
            *(uint2*)&sXhi[base] = hu;
            *(uint2*)&sXlo[base] = lu;
        }
        // ---- W chunk: [k][c] -> Wt [c][k], coalesced loads, bf162 stores ----
        for (int i = tid; i < COUT * (KCH / 2); i += 256) {
            int c  = i % COUT;
            int kp = i / COUT;
            int k  = kp * 2;
            float w0 = W[(size_t)(k0 + k)     * ldw + col0 + c];
            float w1 = W[(size_t)(k0 + k + 1) * ldw + col0 + c];
            __nv_bfloat162 h = __floats2bfloat162_rn(w0, w1);
            __nv_bfloat162 l = __floats2bfloat162_rn(
                w0 - __bfloat162float(h.x), w1 - __bfloat162float(h.y));
            *(__nv_bfloat162*)&sWhi[c * ST + k] = h;
            *(__nv_bfloat162*)&sWlo[c * ST + k] = l;
        }
        __syncthreads();

        // ---- prefetch next X chunk (overlaps with mma phase) ----
        if (k0 + KCH < CIN) {
#pragma unroll
            for (int j = 0; j < XJ; j++) {
                int row = r0 + xr_rl[j];
                xp[j] = (row < nrows)
                    ? *(const float4*)&X[(size_t)row * CIN + k0 + KCH + xr_kq[j] * 4]
                    : make_float4(0.f, 0.f, 0.f, 0.f);
            }
        }

#pragma unroll
        for (int ks = 0; ks < KCH / 16; ks++) {
            unsigned ah0, ah1, ah2, ah3, al0, al1, al2, al3;
            asm volatile("ldmatrix.sync.aligned.m8n8.x4.shared.b16 {%0,%1,%2,%3}, [%4];"
                         : "=r"(ah0), "=r"(ah1), "=r"(ah2), "=r"(ah3)
                         : "r"(aAhi + ks * 32u));
            asm volatile("ldmatrix.sync.aligned.m8n8.x4.shared.b16 {%0,%1,%2,%3}, [%4];"
                         : "=r"(al0), "=r"(al1), "=r"(al2), "=r"(al3)
                         : "r"(aAlo + ks * 32u));
#pragma unroll
            for (int np = 0; np < NT / 2; np++) {
                unsigned bh0, bh1, bh2, bh3, bl0, bl1, bl2, bl3;
                unsigned boff = (unsigned)(np * 16 * ST * 2) + ks * 32u;
                asm volatile("ldmatrix.sync.aligned.m8n8.x4.shared.b16 {%0,%1,%2,%3}, [%4];"
                             : "=r"(bh0), "=r"(bh1), "=r"(bh2), "=r"(bh3)
                             : "r"(aBhi + boff));
                asm volatile("ldmatrix.sync.aligned.m8n8.x4.shared.b16 {%0,%1,%2,%3}, [%4];"
                             : "=r"(bl0), "=r"(bl1), "=r"(bl2), "=r"(bl3)
                             : "r"(aBlo + boff));
                int n0 = np * 2, n1 = np * 2 + 1;
                asm volatile("mma.sync.aligned.m16n8k16.row.col.f32.bf16.bf16.f32 "
                             "{%0,%1,%2,%3},{%4,%5,%6,%7},{%8,%9},{%0,%1,%2,%3};"
                             : "+f"(acc[n0][0]), "+f"(acc[n0][1]), "+f"(acc[n0][2]), "+f"(acc[n0][3])
                             : "r"(ah0), "r"(ah1), "r"(ah2), "r"(ah3), "r"(bh0), "r"(bh1));
                asm volatile("mma.sync.aligned.m16n8k16.row.col.f32.bf16.bf16.f32 "
                             "{%0,%1,%2,%3},{%4,%5,%6,%7},{%8,%9},{%0,%1,%2,%3};"
                             : "+f"(acc[n0][0]), "+f"(acc[n0][1]), "+f"(acc[n0][2]), "+f"(acc[n0][3])
                             : "r"(al0), "r"(al1), "r"(al2), "r"(al3), "r"(bh0), "r"(bh1));
                asm volatile("mma.sync.aligned.m16n8k16.row.col.f32.bf16.bf16.f32 "
                             "{%0,%1,%2,%3},{%4,%5,%6,%7},{%8,%9},{%0,%1,%2,%3};"
                             : "+f"(acc[n0][0]), "+f"(acc[n0][1]), "+f"(acc[n0][2]), "+f"(acc[n0][3])
                             : "r"(ah0), "r"(ah1), "r"(ah2), "r"(ah3), "r"(bl0), "r"(bl1));
                asm volatile("mma.sync.aligned.m16n8k16.row.col.f32.bf16.bf16.f32 "
                             "{%0,%1,%2,%3},{%4,%5,%6,%7},{%8,%9},{%0,%1,%2,%3};"
                             : "+f"(acc[n1][0]), "+f"(acc[n1][1]), "+f"(acc[n1][2]), "+f"(acc[n1][3])
                             : "r"(ah0), "r"(ah1), "r"(ah2), "r"(ah3), "r"(bh2), "r"(bh3));
                asm volatile("mma.sync.aligned.m16n8k16.row.col.f32.bf16.bf16.f32 "
                             "{%0,%1,%2,%3},{%4,%5,%6,%7},{%8,%9},{%0,%1,%2,%3};"
                             : "+f"(acc[n1][0]), "+f"(acc[n1][1]), "+f"(acc[n1][2]), "+f"(acc[n1][3])
                             : "r"(al0), "r"(al1), "r"(al2), "r"(al3), "r"(bh2), "r"(bh3));
                asm volatile("mma.sync.aligned.m16n8k16.row.col.f32.bf16.bf16.f32 "
                             "{%0,%1,%2,%3},{%4,%5,%6,%7},{%8,%9},{%0,%1,%2,%3};"
                             : "+f"(acc[n1][0]), "+f"(acc[n1][1]), "+f"(acc[n1][2]), "+f"(acc[n1][3])
                             : "r"(ah0), "r"(ah1), "r"(ah2), "r"(ah3), "r"(bl2), "r"(bl3));
            }
        }
        __syncthreads();
    }

    // ---- epilogue ----
    int gr0 = r0 + wid * 16 + (lane >> 2);
    int gr1 = gr0 + 8;

    if (EPI == 2) {
        int gmin = g_nodeg[r0 < nrows ? r0 : nrows - 1];
        int glast = g_nodeg[min(r0 + 127, nrows - 1)];
        int g0 = (gr0 < nrows) ? g_nodeg[gr0] : -1;
        int g1 = (gr1 < nrows) ? g_nodeg[gr1] : -1;
        int i0 = g0 - gmin, i1 = g1 - gmin;
#pragma unroll
        for (int n = 0; n < NT; n++) {
            int col = col0 + n * 8 + (lane & 3) * 2;
            float b0 = bias[col], b1 = bias[col + 1];
            float v0 = fmaxf(acc[n][0] + b0, 0.f);
            float v1 = fmaxf(acc[n][1] + b1, 0.f);
            float v2 = fmaxf(acc[n][2] + b0, 0.f);
            float v3 = fmaxf(acc[n][3] + b1, 0.f);
            if (g0 >= 0) {
                if ((unsigned)i0 < 32u) {
                    atomicMax(&sPool[i0 * 128 + col],     __float_as_int(v0));
                    atomicMax(&sPool[i0 * 128 + col + 1], __float_as_int(v1));
                } else {
                    atomicMax(&g_pool[g0 * 128 + col],     __float_as_int(v0));
                    atomicMax(&g_pool[g0 * 128 + col + 1], __float_as_int(v1));
                }
            }
            if (g1 >= 0) {
                if ((unsigned)i1 < 32u) {
                    atomicMax(&sPool[i1 * 128 + col],     __float_as_int(v2));
                    atomicMax(&sPool[i1 * 128 + col + 1], __float_as_int(v3));
                } else {
                    atomicMax(&g_pool[g1 * 128 + col],     __float_as_int(v2));
                    atomicMax(&g_pool[g1 * 128 + col + 1], __float_as_int(v3));
                }
            }
        }
        __syncthreads();
        int span = min(glast - gmin, 31);
        int total = (span + 1) * 128;
        for (int i = tid; i < total; i += 256) {
            int b = sPool[i];
            if (b != 0)
                atomicMax(&g_pool[(gmin + i / 128) * 128 + (i & 127)], b);
        }
    } else {
#pragma unroll
        for (int n = 0; n < NT; n++) {
            int col = col0 + n * 8 + (lane & 3) * 2;
            float v0 = acc[n][0], v1 = acc[n][1], v2 = acc[n][2], v3 = acc[n][3];
            if (EPI >= 1) {
                float b0 = bias[col], b1 = bias[col + 1];
                v0 += b0; v1 += b1; v2 += b0; v3 += b1;
                if (EPI == 1) {
                    v0 = fmaxf(v0, 0.f); v1 = fmaxf(v1, 0.f);
                    v2 = fmaxf(v2, 0.f); v3 = fmaxf(v3, 0.f);
                }
            }
            if (gr0 < nrows) *(float2*)&Y[(size_t)gr0 * ldy + col] = make_float2(v0, v1);
            if (gr1 < nrows) *(float2*)&Y[(size_t)gr1 * ldy + col] = make_float2(v2, v3);
        }
    }
}

// ---------------- CSR gather (vectorized): O = P @ H ---------------------
template<int C, bool EPI>
__global__ __launch_bounds__(256)
void gather_kernel(const float* __restrict__ H, float* __restrict__ O,
                   const float* __restrict__ bias) {
    constexpr int L = C / 4;
    int idx = blockIdx.x * 256 + threadIdx.x;
    int node = idx / L;
    int c4 = (idx % L) * 4;
    if (node >= NN) return;
    int s = g_rowptr[node], e = g_rowptr[node + 1];
    float ax = 0.f, ay = 0.f, az = 0.f, aw = 0.f;
    for (int k = s; k < e; k++) {
        float2 ew = g_csr2[k];
        int src = __float_as_int(ew.x);
        float w = ew.y;
        float4 h = *(const float4*)&H[(size_t)src * C + c4];
        ax += h.x * w; ay += h.y * w; az += h.z * w; aw += h.w * w;
    }
    float d = g_dis[node];
    float d2 = d * d;
    float4 hn = *(const float4*)&H[(size_t)node * C + c4];
    float4 o;
    o.x = d * ax + hn.x * d2;
    o.y = d * ay + hn.y * d2;
    o.z = d * az + hn.z * d2;
    o.w = d * aw + hn.w * d2;
    if (EPI) {
        float4 b = *(const float4*)&bias[c4];
        o.x = fmaxf(o.x + b.x, 0.f);
        o.y = fmaxf(o.y + b.y, 0.f);
        o.z = fmaxf(o.z + b.z, 0.f);
        o.w = fmaxf(o.w + b.w, 0.f);
    }
    *(float4*)&O[(size_t)node * C + c4] = o;
}

// ---------------- launch ----------------
extern "C" void kernel_launch(void* const* d_in, const int* in_sizes, int n_in,
                              void* d_out, int out_size) {
    const float* x     = (const float*)d_in[0];
    const void*  ei    = d_in[1];
    const void*  batch = d_in[2];
    const float* nw    = (const float*)d_in[3];
    const float* nbi   = (const float*)d_in[4];
    const float* W1    = (const float*)d_in[5];
    const float* b1    = (const float*)d_in[6];
    const float* W2    = (const float*)d_in[7];
    const float* b2    = (const float*)d_in[8];
    const float* W3    = (const float*)d_in[9];
    const float* b3    = (const float*)d_in[10];
    const float* l1W   = (const float*)d_in[11];
    const float* l1b   = (const float*)d_in[12];
    const float* l2W   = (const float*)d_in[13];
    const float* l2b   = (const float*)d_in[14];
    float* out = (float*)d_out;

    void *pA, *pB, *pC, *pPool;
    cudaGetSymbolAddress(&pA, g_bufA);
    cudaGetSymbolAddress(&pB, g_bufB);
    cudaGetSymbolAddress(&pC, g_bufC);
    cudaGetSymbolAddress(&pPool, g_pool);
    float* fA = (float*)pA;
    float* fB = (float*)pB;
    float* fC = (float*)pC;
    const float* poolf = (const float*)pPool;   // bit-pattern of >=0 floats

    init_kernel<<<(GG * 128 + 255) / 256, 256>>>(ei, batch);
    graph_kernel<<<(EE + 255) / 256, 256>>>(batch, ei);

    scan1_kernel<<<NBS, SCAN_B>>>();
    scan3_kernel<<<(NN + 255) / 256, 256>>>();
    fill_kernel<<<(EE + 255) / 256, 256>>>(ei);

    stats_kernel<<<GG, 128>>>(x, nw, nbi);

    const int GB = (NN + 127) / 128;

    // layer 1: (norm ∘ x) @ W1 -> B(32ch); propagate w/ bias+relu -> A
    mma_gemm<128, 32, true, 0><<<GB, 256>>>(x, W1, 32, nullptr, fB, 32, NN);
    gather_kernel<32, true><<<(NN * 8 + 255) / 256, 256>>>(fB, fA, b1);

    // layer 2: propagate (32ch) -> C; GEMM 32->64 w/ bias+relu -> B
    gather_kernel<32, false><<<(NN * 8 + 255) / 256, 256>>>(fA, fC, nullptr);
    mma_gemm<32, 64, false, 1><<<GB, 256>>>(fC, W2, 64, b2, fB, 64, NN);

    // layer 3: propagate (64ch) -> A; GEMM 64->128 + bias+relu + FUSED pool
    gather_kernel<64, false><<<(NN * 16 + 255) / 256, 256>>>(fB, fA, nullptr);
    mma_gemm<64, 128, false, 2><<<GB, 256>>>(fA, W3, 128, b3, nullptr, 128, NN);

    // head: pooled[G,128] @ l1W (+relu) -> B[G,256]; @ l2W (+bias) -> out
    {
        dim3 grid1((GG + 127) / 128, 4);
        mma_gemm<128, 64, false, 1><<<grid1, 256>>>(poolf, l1W, 256, l1b, fB, 256, GG);
        dim3 grid2((GG + 127) / 128, 2);
        mma_gemm<256, 64, false, 3><<<grid2, 256>>>(fB, l2W, 128, l2b, out, 128, GG);
    }
}